// round 11
// baseline (speedup 1.0000x reference)
#include <cuda_runtime.h>
#include <math.h>

// Problem constants
#define B_TOT 256
#define AIN   8
#define MUL   1024
#define NK    20
#define NO    16

// Persistent scratch (device globals; allocation-free)
__device__ __align__(16) float g_c[NK * MUL];
__device__ __align__(16) float g_b[NK * MUL];
__device__ __align__(16) float g_bpart[16 * NK * MUL];
__device__ __align__(16) float g_wv[B_TOT * NK * AIN];
__device__ __align__(16) float g_yp[16 * B_TOT * NK * AIN];  // y partials [mt][b][k][a]

// Packed f32x2 FMA
#define FMA2(acc, a, b) \
    asm("fma.rn.f32x2 %0, %1, %2, %0;" : "+l"(acc) : "l"(a), "l"(b))

__device__ __forceinline__ float pair_sum(unsigned long long u) {
    float lo = __uint_as_float((unsigned)(u & 0xffffffffu));
    float hi = __uint_as_float((unsigned)(u >> 32));
    return lo + hi;
}

// ---------------------------------------------------------------------------
// YP kernel (U-shaped): grid (16 m-tiles, 16 b-slices), 320 thr = (bl, k).
// y-partial[b][k][a] = sum_{m in tile} c[k][m] * x[b][m][a].
// Flat inner loop: LDS.64 c (broadcast) + 2x LDS.128 x (broadcast) + 4 FMA2.
// No shuffles, no mid-kernel barriers. Partials to g_yp.
// ---------------------------------------------------------------------------
#define YP_THREADS 320

__global__ void __launch_bounds__(YP_THREADS, 2)
yp_kernel(const float* __restrict__ x, int uniform_c)
{
    __shared__ float xs[16 * 512];               // [bl][m][a]  32 KB
    __shared__ unsigned long long cs2[64 * 20];  // [m][k] duplicated-pair c  10 KB

    const int tid = threadIdx.x;
    const int mt  = blockIdx.x;                  // m-tile (64 m's)
    const int bs  = blockIdx.y;                  // batch slice (16 batches)

    // stage x: natural layout, pure float4 copies (same as U kernel)
    for (int i = tid; i < 2048; i += YP_THREADS) {
        int bi = i >> 7, rr = i & 127;
        ((float4*)(xs + bi * 512))[rr] =
            ((const float4*)(x + (size_t)(bs * 16 + bi) * 8192 + mt * 512))[rr];
    }
    // stage c duplicated into f32x2 pairs, [m][k] layout
    if (uniform_c) {
        unsigned u = __float_as_uint(1.0f / 1024.0f);
        unsigned long long pk = (unsigned long long)u | ((unsigned long long)u << 32);
        for (int i = tid; i < 1280; i += YP_THREADS) cs2[i] = pk;
    } else {
        for (int i = tid; i < 1280; i += YP_THREADS) {
            int k = i >> 6, m = i & 63;          // coalesced read per k-row
            unsigned u = __float_as_uint(g_c[k * MUL + mt * 64 + m]);
            cs2[m * 20 + k] = (unsigned long long)u | ((unsigned long long)u << 32);
        }
    }
    __syncthreads();

    const int bl = tid / 20, k = tid % 20;
    const float* xb = xs + bl * 512;

    unsigned long long a0 = 0ull, a1 = 0ull, a2 = 0ull, a3 = 0ull;
    #pragma unroll 8
    for (int m = 0; m < 64; m++) {
        unsigned long long cv = cs2[m * 20 + k];
        ulonglong2 xA = *(const ulonglong2*)(xb + m * 8);
        ulonglong2 xB = *(const ulonglong2*)(xb + m * 8 + 4);
        FMA2(a0, xA.x, cv); FMA2(a1, xA.y, cv);
        FMA2(a2, xB.x, cv); FMA2(a3, xB.y, cv);
    }

    // store raw packed pairs = natural a-order floats
    unsigned long long* dst = (unsigned long long*)
        (g_yp + ((size_t)(mt * 256 + bs * 16 + bl) * 20 + k) * 8);
    dst[0] = a0; dst[1] = a1; dst[2] = a2; dst[3] = a3;
}

// ---------------------------------------------------------------------------
// Tail kernel: 256 blocks (one per batch), 320 threads.
// Combine 16 m-tile partials -> y, then s = W y, squash (class-sum per
// reference), v, and wv = W^T v (or final output).
// ---------------------------------------------------------------------------
__global__ void __launch_bounds__(320, 4)
tail_kernel(const float* __restrict__ W, float* __restrict__ out, int final_it)
{
    __shared__ float ysm[NK * AIN];
    __shared__ float svm[NK * NO];
    __shared__ float cqm[NO];

    const int tid = threadIdx.x;
    const int b   = blockIdx.x;

    if (tid < 160) {
        float f = 0.f;
        #pragma unroll
        for (int mtt = 0; mtt < 16; mtt++)
            f += g_yp[(size_t)(mtt * 256 + b) * 160 + tid];
        ysm[tid] = f;
    }
    __syncthreads();

    const int k = tid >> 4, o = tid & 15;
    const float* wk = W + tid * 8;               // (k*16+o)*8 == tid*8
    const float* yk = ysm + k * 8;
    float s = 0.f;
    #pragma unroll
    for (int a = 0; a < 8; a++) s += wk[a] * yk[a];
    svm[tid] = s;
    __syncthreads();

    if (tid < NO) {
        float msq = 0.f;
        #pragma unroll
        for (int kk = 0; kk < NK; kk++) {
            float t = svm[kk * NO + tid];
            msq += t * t;
        }
        cqm[tid] = msq / ((1.f + msq) * sqrtf(msq));
    }
    __syncthreads();

    float v = cqm[o] * s;
    if (final_it) {
        out[(size_t)b * 320 + tid] = v;          // coalesced
    } else {
        svm[tid] = v;
        __syncthreads();
        if (tid < 160) {
            int kk = tid >> 3, aa = tid & 7;
            float acc = 0.f;
            #pragma unroll
            for (int oo = 0; oo < 16; oo++)
                acc += W[(kk * 16 + oo) * 8 + aa] * svm[kk * 16 + oo];
            g_wv[(size_t)b * 160 + tid] = acc;
        }
    }
}

// ---------------------------------------------------------------------------
// Update kernel (R10, unchanged): 256 blocks = (16 m-tiles x 16 slices).
// partial[m,k] = sum_{b in slice} sum_a x[b,m,a]*wv[b,k,a] / 256
// ---------------------------------------------------------------------------
#define U_THREADS 320

__global__ void __launch_bounds__(U_THREADS)
update_kernel(const float* __restrict__ x)
{
    __shared__ float xsU[8 * 512];
    __shared__ float wvs[8 * 160];

    const int tid   = threadIdx.x;
    const int m0    = blockIdx.x * 64;
    const int bbase = blockIdx.y * 16;
    const int mi4   = tid / NK;
    const int k     = tid % NK;

    unsigned long long acc[4];
    #pragma unroll
    for (int i = 0; i < 4; i++) acc[i] = 0ull;

    for (int c0 = 0; c0 < 16; c0 += 8) {
        __syncthreads();
        for (int i = tid; i < 1024; i += U_THREADS) {
            int bi = i >> 7, rr = i & 127;
            ((float4*)(xsU + bi * 512))[rr] =
                ((const float4*)(x + (size_t)(bbase + c0 + bi) * 8192 + m0 * 8))[rr];
        }
        for (int i = tid; i < 320; i += U_THREADS) {
            int bi = i / 40, rr = i % 40;
            ((float4*)(wvs + bi * 160))[rr] =
                ((const float4*)(g_wv + (size_t)(bbase + c0 + bi) * 160))[rr];
        }
        __syncthreads();

        #pragma unroll
        for (int bi = 0; bi < 8; bi++) {
            const ulonglong2* wp = (const ulonglong2*)(wvs + bi * 160 + k * 8);
            ulonglong2 wA = wp[0], wB = wp[1];
            const ulonglong2* xp = (const ulonglong2*)(xsU + bi * 512 + mi4 * 32);
            #pragma unroll
            for (int mm = 0; mm < 4; mm++) {
                ulonglong2 xA = xp[mm * 2];
                ulonglong2 xB = xp[mm * 2 + 1];
                FMA2(acc[mm], xA.x, wA.x);
                FMA2(acc[mm], xA.y, wA.y);
                FMA2(acc[mm], xB.x, wB.x);
                FMA2(acc[mm], xB.y, wB.y);
            }
        }
    }

    float* dst = g_bpart + (size_t)blockIdx.y * (NK * MUL) + k * MUL + m0 + mi4 * 4;
    #pragma unroll
    for (int mm = 0; mm < 4; mm++) dst[mm] = pair_sum(acc[mm]) * (1.0f / 256.0f);
}

// ---------------------------------------------------------------------------
// Softmax kernel (R10, unchanged): 20 blocks x 1024 threads.
// ---------------------------------------------------------------------------
__global__ void __launch_bounds__(1024)
softmax_kernel(int accum)
{
    const int k = blockIdx.x;
    const int t = threadIdx.x;
    const int lane = t & 31, wp = t >> 5;
    __shared__ float red[32];
    __shared__ float bc;

    float b = accum ? g_b[k * MUL + t] : 0.f;
    #pragma unroll
    for (int p = 0; p < 16; p++) b += g_bpart[p * NK * MUL + k * MUL + t];
    g_b[k * MUL + t] = b;

    float mx = b;
    #pragma unroll
    for (int off = 16; off; off >>= 1)
        mx = fmaxf(mx, __shfl_xor_sync(0xffffffffu, mx, off));
    if (lane == 0) red[wp] = mx;
    __syncthreads();
    if (t < 32) {
        float m = red[t];
        #pragma unroll
        for (int off = 16; off; off >>= 1)
            m = fmaxf(m, __shfl_xor_sync(0xffffffffu, m, off));
        if (t == 0) bc = m;
    }
    __syncthreads();
    mx = bc;

    float e = expf(b - mx);
    float s = e;
    #pragma unroll
    for (int off = 16; off; off >>= 1)
        s += __shfl_xor_sync(0xffffffffu, s, off);
    __syncthreads();
    if (lane == 0) red[wp] = s;
    __syncthreads();
    if (t < 32) {
        float ss = red[t];
        #pragma unroll
        for (int off = 16; off; off >>= 1)
            ss += __shfl_xor_sync(0xffffffffu, ss, off);
        if (t == 0) bc = ss;
    }
    __syncthreads();

    g_c[k * MUL + t] = e * (1.0f / bc);
}

// ---------------------------------------------------------------------------
extern "C" void kernel_launch(void* const* d_in, const int* in_sizes, int n_in,
                              void* d_out, int out_size)
{
    const float* x = (const float*)d_in[0];   // [256][1024][8] flat view
    const float* W = (const float*)d_in[1];   // [20][16][8]
    float* out = (float*)d_out;               // [256][20][16][1]

    dim3 ypgrid(16, 16);
    dim3 ugrid(16, 16);

    // iteration 0 (uniform c)
    yp_kernel<<<ypgrid, YP_THREADS>>>(x, 1);
    tail_kernel<<<B_TOT, 320>>>(W, out, 0);
    update_kernel<<<ugrid, U_THREADS>>>(x);
    softmax_kernel<<<NK, 1024>>>(0);

    // iteration 1
    yp_kernel<<<ypgrid, YP_THREADS>>>(x, 0);
    tail_kernel<<<B_TOT, 320>>>(W, out, 0);
    update_kernel<<<ugrid, U_THREADS>>>(x);
    softmax_kernel<<<NK, 1024>>>(1);

    // iteration 2 (final -> write v)
    yp_kernel<<<ypgrid, YP_THREADS>>>(x, 0);
    tail_kernel<<<B_TOT, 320>>>(W, out, 1);
}

// round 12
// speedup vs baseline: 1.3198x; 1.3198x over previous
#include <cuda_runtime.h>
#include <math.h>

// Problem constants
#define B_TOT 256
#define AIN   8
#define MUL   1024
#define NK    20
#define NO    16
#define PLF   1036          // plane stride (floats): 16B-aligned, kills STS h-conflict

// Persistent scratch (device globals; allocation-free)
__device__ __align__(16) float g_c[NK * MUL];
__device__ __align__(16) float g_b[NK * MUL];
__device__ __align__(16) float g_bpart[16 * NK * MUL];
__device__ __align__(16) float g_wv[B_TOT * NK * AIN];
__device__ __align__(16) float g_xsum[B_TOT * AIN];     // per-batch plane sums

// Packed f32x2 FMA
#define FMA2(acc, a, b) \
    asm("fma.rn.f32x2 %0, %1, %2, %0;" : "+l"(acc) : "l"(a), "l"(b))

__device__ __forceinline__ float pair_sum(unsigned long long u) {
    float lo = __uint_as_float((unsigned)(u & 0xffffffffu));
    float hi = __uint_as_float((unsigned)(u >> 32));
    return lo + hi;
}

#define WARP_RED_SUM(v)                                   \
  do {                                                    \
    v += __shfl_xor_sync(0xffffffffu, v, 16);             \
    v += __shfl_xor_sync(0xffffffffu, v, 8);              \
    v += __shfl_xor_sync(0xffffffffu, v, 4);              \
    v += __shfl_xor_sync(0xffffffffu, v, 2);              \
    v += __shfl_xor_sync(0xffffffffu, v, 1);              \
  } while (0)

// ---------------------------------------------------------------------------
// prep_xsum: 256 blocks (one per batch) x 256 threads.
// g_xsum[b][a] = sum_m x[b][m][a]. Even threads carry a0-3, odd a4-7.
// ---------------------------------------------------------------------------
__global__ void __launch_bounds__(256)
prep_xsum(const float* __restrict__ x)
{
    __shared__ float red[8][8];
    const int t = threadIdx.x;
    const int b = blockIdx.x;
    const int w = t >> 5, lane = t & 31;

    const float4* xs4 = (const float4*)(x + (size_t)b * 8192);
    float4 acc = make_float4(0.f, 0.f, 0.f, 0.f);
    #pragma unroll
    for (int i = 0; i < 8; i++) {
        float4 v = xs4[t + i * 256];
        acc.x += v.x; acc.y += v.y; acc.z += v.z; acc.w += v.w;
    }
    // reduce among same-parity lanes (parity == a-half)
    #pragma unroll
    for (int off = 2; off <= 16; off <<= 1) {
        acc.x += __shfl_xor_sync(0xffffffffu, acc.x, off);
        acc.y += __shfl_xor_sync(0xffffffffu, acc.y, off);
        acc.z += __shfl_xor_sync(0xffffffffu, acc.z, off);
        acc.w += __shfl_xor_sync(0xffffffffu, acc.w, off);
    }
    if (lane < 2) {
        red[w][lane * 4 + 0] = acc.x;
        red[w][lane * 4 + 1] = acc.y;
        red[w][lane * 4 + 2] = acc.z;
        red[w][lane * 4 + 3] = acc.w;
    }
    __syncthreads();
    if (t < 8) {
        float s = 0.f;
        #pragma unroll
        for (int i = 0; i < 8; i++) s += red[i][t];
        g_xsum[b * 8 + t] = s;
    }
}

// ---------------------------------------------------------------------------
// u0_kernel: grid (16 m-tiles x 16 b-slices), 320 thr. Iteration-0 fused:
// y0 = xsum/1024, tail (s = W y0, squash, v, wv in smem), then agree partials.
// ---------------------------------------------------------------------------
#define U_THREADS 320

__global__ void __launch_bounds__(U_THREADS)
u0_kernel(const float* __restrict__ x, const float* __restrict__ W)
{
    __shared__ float wvs[16 * 160];      // 2560
    __shared__ float svm[16 * 320];      // 5120 (xsU reuses this after tail)
    __shared__ float ysm[16 * 8];        // 128
    __shared__ float cqm[16 * 16];       // 256
    float* xsU = svm;                    // [8][512] staging region (4096 <= 5120)

    const int tid   = threadIdx.x;
    const int m0    = blockIdx.x * 64;
    const int bbase = blockIdx.y * 16;

    // y0 for 16 batches
    if (tid < 128) {
        int bb = tid >> 3, a = tid & 7;
        ysm[tid] = g_xsum[(bbase + bb) * 8 + a] * (1.0f / 1024.0f);
    }
    __syncthreads();

    // s = W y0 for all 16 batches (thread = (k,o))
    {
        float wreg[8];
        const float4* wp4 = (const float4*)(W + tid * 8);
        float4 wA = wp4[0], wB = wp4[1];
        wreg[0] = wA.x; wreg[1] = wA.y; wreg[2] = wA.z; wreg[3] = wA.w;
        wreg[4] = wB.x; wreg[5] = wB.y; wreg[6] = wB.z; wreg[7] = wB.w;
        #pragma unroll
        for (int bb = 0; bb < 16; bb++) {
            const float* y = ysm + bb * 8;
            float s = 0.f;
            #pragma unroll
            for (int a = 0; a < 8; a++) s += wreg[a] * y[a];
            svm[bb * 320 + tid] = s;
        }
    }
    __syncthreads();

    // squash coefficients (sum over classes, per reference)
    if (tid < 256) {
        int bb = tid >> 4, o = tid & 15;
        float msq = 0.f;
        #pragma unroll
        for (int kk = 0; kk < NK; kk++) {
            float t = svm[bb * 320 + kk * 16 + o];
            msq += t * t;
        }
        cqm[tid] = msq / ((1.f + msq) * sqrtf(msq));
    }
    __syncthreads();

    // v = coeff * s (in place)
    {
        const int o = tid & 15;
        #pragma unroll
        for (int bb = 0; bb < 16; bb++)
            svm[bb * 320 + tid] *= cqm[bb * 16 + o];
    }
    __syncthreads();

    // wv[b][k][a] = sum_o W[k,o,a] * v[b,k,o]
    {
        const int r   = tid % 160;
        const int bb0 = tid / 160;           // 0 or 1
        const int kk  = r >> 3, aa = r & 7;
        float w16[16];
        #pragma unroll
        for (int oo = 0; oo < 16; oo++) w16[oo] = W[(kk * 16 + oo) * 8 + aa];
        #pragma unroll
        for (int s8 = 0; s8 < 8; s8++) {
            int bb = bb0 + s8 * 2;
            float acc = 0.f;
            #pragma unroll
            for (int oo = 0; oo < 16; oo++)
                acc += w16[oo] * svm[bb * 320 + kk * 16 + oo];
            wvs[bb * 160 + r] = acc;
        }
    }

    // agree partial loop (svm region reused as xsU; barrier-separated)
    const int mi4 = tid / NK;
    const int k   = tid % NK;
    unsigned long long acc[4];
    #pragma unroll
    for (int i = 0; i < 4; i++) acc[i] = 0ull;

    for (int c0 = 0; c0 < 16; c0 += 8) {
        __syncthreads();
        for (int i = tid; i < 1024; i += U_THREADS) {
            int bi = i >> 7, rr = i & 127;
            ((float4*)(xsU + bi * 512))[rr] =
                ((const float4*)(x + (size_t)(bbase + c0 + bi) * 8192 + m0 * 8))[rr];
        }
        __syncthreads();

        #pragma unroll
        for (int bi = 0; bi < 8; bi++) {
            const ulonglong2* wp = (const ulonglong2*)(wvs + (c0 + bi) * 160 + k * 8);
            ulonglong2 wA = wp[0], wB = wp[1];
            const ulonglong2* xp = (const ulonglong2*)(xsU + bi * 512 + mi4 * 32);
            #pragma unroll
            for (int mm = 0; mm < 4; mm++) {
                ulonglong2 xA = xp[mm * 2];
                ulonglong2 xB = xp[mm * 2 + 1];
                FMA2(acc[mm], xA.x, wA.x);
                FMA2(acc[mm], xA.y, wA.y);
                FMA2(acc[mm], xB.x, wB.x);
                FMA2(acc[mm], xB.y, wB.y);
            }
        }
    }

    float* dst = g_bpart + (size_t)blockIdx.y * (NK * MUL) + k * MUL + m0 + mi4 * 4;
    #pragma unroll
    for (int mm = 0; mm < 4; mm++) dst[mm] = pair_sum(acc[mm]) * (1.0f / 256.0f);
}

// F smem layout (floats)
#define OFF_CS   16576      // cs  [20][1024]   20480
#define OFF_Y    37056      // ysm [2][20][8]     320
#define OFF_SV   37376      // svm [2][320]       640
#define OFF_CQ   38016      // cqm [2][16]         32
#define F_FLOATS 38048
#define F_THREADS 640

// ---------------------------------------------------------------------------
// F kernel (R10, non-uniform only): block = batch-pair. Stage x (transposed)
// + c into SMEM, y = c^T x from SMEM, tail: s = W y, squash, v, wv/out.
// ---------------------------------------------------------------------------
__global__ void __launch_bounds__(F_THREADS, 1)
fused_kernel(const float* __restrict__ x, const float* __restrict__ W,
             float* __restrict__ out, int final_iter)
{
    extern __shared__ float sm[];
    float* xs  = sm;                 // [2][8][PLF]
    float* cs  = sm + OFF_CS;        // [20][1024]
    float* ysm = sm + OFF_Y;
    float* svm = sm + OFF_SV;
    float* cqm = sm + OFF_CQ;

    const int tid = threadIdx.x;
    const int b0  = blockIdx.x * 2;

    // stage x transposed (f4 load -> 4 scalar STS to planes)
    {
        const float4* xsrc = (const float4*)(x + (size_t)b0 * 8192);
        #pragma unroll 2
        for (int i = tid; i < 4096; i += F_THREADS) {
            int bl = i >> 11, f = i & 2047;
            int m = f >> 1, half = f & 1;
            float4 v = xsrc[i];
            float* base = xs + (bl * 8 + half * 4) * PLF + m;
            base[0 * PLF] = v.x; base[1 * PLF] = v.y;
            base[2 * PLF] = v.z; base[3 * PLF] = v.w;
        }
    }
    // stage c (bulk f4 copy)
    {
        const float4* csrc = (const float4*)g_c;
        float4* cdst = (float4*)cs;
        #pragma unroll
        for (int i = 0; i < 8; i++) cdst[tid + i * F_THREADS] = csrc[tid + i * F_THREADS];
    }
    __syncthreads();

    // y phase: 20 warps = (bl, kq, ah); 4 classes x 4 atoms, f32x2
    {
        const int w = tid >> 5, lane = tid & 31;
        const int bl = w / 10;
        const int r  = w % 10;
        const int k0 = (r >> 1) * 4;
        const int a0 = (r & 1) * 4;

        unsigned long long acc[4][4];
        #pragma unroll
        for (int kk = 0; kk < 4; kk++)
            #pragma unroll
            for (int aa = 0; aa < 4; aa++) acc[kk][aa] = 0ull;

        #pragma unroll 2
        for (int j = 0; j < 8; j++) {
            const int m = j * 128 + lane * 4;
            ulonglong2 ck0 = *(const ulonglong2*)(cs + (k0 + 0) * MUL + m);
            ulonglong2 ck1 = *(const ulonglong2*)(cs + (k0 + 1) * MUL + m);
            ulonglong2 ck2 = *(const ulonglong2*)(cs + (k0 + 2) * MUL + m);
            ulonglong2 ck3 = *(const ulonglong2*)(cs + (k0 + 3) * MUL + m);
            #pragma unroll
            for (int aa = 0; aa < 4; aa++) {
                ulonglong2 xv = *(const ulonglong2*)(xs + (bl * 8 + a0 + aa) * PLF + m);
                FMA2(acc[0][aa], ck0.x, xv.x); FMA2(acc[0][aa], ck0.y, xv.y);
                FMA2(acc[1][aa], ck1.x, xv.x); FMA2(acc[1][aa], ck1.y, xv.y);
                FMA2(acc[2][aa], ck2.x, xv.x); FMA2(acc[2][aa], ck2.y, xv.y);
                FMA2(acc[3][aa], ck3.x, xv.x); FMA2(acc[3][aa], ck3.y, xv.y);
            }
        }
        #pragma unroll
        for (int kk = 0; kk < 4; kk++) {
            #pragma unroll
            for (int aa = 0; aa < 4; aa++) {
                float v = pair_sum(acc[kk][aa]);
                WARP_RED_SUM(v);
                if (lane == 0) ysm[bl * 160 + (k0 + kk) * 8 + a0 + aa] = v;
            }
        }
        __syncthreads();
    }

    // tail: s = W y, squash (class-sum per reference), v, wv/out
    const int bl = tid / 320, r = tid % 320;
    const int k = r >> 4, o = r & 15;
    {
        const float* wk = W + r * 8;
        const float* yk = ysm + bl * 160 + k * 8;
        float s = 0.f;
        #pragma unroll
        for (int a = 0; a < 8; a++) s += wk[a] * yk[a];
        svm[bl * 320 + r] = s;
        __syncthreads();

        if (tid < 32) {
            int bb = tid >> 4, oo = tid & 15;
            float msq = 0.f;
            #pragma unroll
            for (int kk = 0; kk < NK; kk++) {
                float t = svm[bb * 320 + kk * 16 + oo];
                msq += t * t;
            }
            cqm[bb * 16 + oo] = msq / ((1.f + msq) * sqrtf(msq));
        }
        __syncthreads();

        float v = cqm[bl * 16 + o] * s;
        if (final_iter) {
            out[(size_t)(b0 + bl) * 320 + r] = v;     // coalesced
        } else {
            svm[bl * 320 + r] = v;
            __syncthreads();
            if (tid < 320) {
                int bb = tid / 160, rr = tid % 160;
                int kk = rr >> 3, aa = rr & 7;
                float acc = 0.f;
                #pragma unroll
                for (int oo = 0; oo < 16; oo++)
                    acc += W[(kk * 16 + oo) * 8 + aa] * svm[bb * 320 + kk * 16 + oo];
                g_wv[(size_t)(b0 + bb) * 160 + rr] = acc;
            }
        }
    }
}

// ---------------------------------------------------------------------------
// Update kernel (R10, unchanged): 256 blocks = (16 m-tiles x 16 slices).
// ---------------------------------------------------------------------------
__global__ void __launch_bounds__(U_THREADS)
update_kernel(const float* __restrict__ x)
{
    __shared__ float xsU[8 * 512];
    __shared__ float wvs[8 * 160];

    const int tid   = threadIdx.x;
    const int m0    = blockIdx.x * 64;
    const int bbase = blockIdx.y * 16;
    const int mi4   = tid / NK;
    const int k     = tid % NK;

    unsigned long long acc[4];
    #pragma unroll
    for (int i = 0; i < 4; i++) acc[i] = 0ull;

    for (int c0 = 0; c0 < 16; c0 += 8) {
        __syncthreads();
        for (int i = tid; i < 1024; i += U_THREADS) {
            int bi = i >> 7, rr = i & 127;
            ((float4*)(xsU + bi * 512))[rr] =
                ((const float4*)(x + (size_t)(bbase + c0 + bi) * 8192 + m0 * 8))[rr];
        }
        for (int i = tid; i < 320; i += U_THREADS) {
            int bi = i / 40, rr = i % 40;
            ((float4*)(wvs + bi * 160))[rr] =
                ((const float4*)(g_wv + (size_t)(bbase + c0 + bi) * 160))[rr];
        }
        __syncthreads();

        #pragma unroll
        for (int bi = 0; bi < 8; bi++) {
            const ulonglong2* wp = (const ulonglong2*)(wvs + bi * 160 + k * 8);
            ulonglong2 wA = wp[0], wB = wp[1];
            const ulonglong2* xp = (const ulonglong2*)(xsU + bi * 512 + mi4 * 32);
            #pragma unroll
            for (int mm = 0; mm < 4; mm++) {
                ulonglong2 xA = xp[mm * 2];
                ulonglong2 xB = xp[mm * 2 + 1];
                FMA2(acc[mm], xA.x, wA.x);
                FMA2(acc[mm], xA.y, wA.y);
                FMA2(acc[mm], xB.x, wB.x);
                FMA2(acc[mm], xB.y, wB.y);
            }
        }
    }

    float* dst = g_bpart + (size_t)blockIdx.y * (NK * MUL) + k * MUL + m0 + mi4 * 4;
    #pragma unroll
    for (int mm = 0; mm < 4; mm++) dst[mm] = pair_sum(acc[mm]) * (1.0f / 256.0f);
}

// ---------------------------------------------------------------------------
// Softmax kernel: 20 blocks x 1024 threads, NO max subtraction (inputs
// bounded; exp safe in fp32; mathematically identical).
// ---------------------------------------------------------------------------
__global__ void __launch_bounds__(1024)
softmax_kernel(int accum)
{
    const int k = blockIdx.x;
    const int t = threadIdx.x;
    const int lane = t & 31, wp = t >> 5;
    __shared__ float red[32];
    __shared__ float bc;

    float b = accum ? g_b[k * MUL + t] : 0.f;
    #pragma unroll
    for (int p = 0; p < 16; p++) b += g_bpart[p * NK * MUL + k * MUL + t];
    g_b[k * MUL + t] = b;

    float e = expf(b);
    float s = e;
    #pragma unroll
    for (int off = 16; off; off >>= 1)
        s += __shfl_xor_sync(0xffffffffu, s, off);
    if (lane == 0) red[wp] = s;
    __syncthreads();
    if (t < 32) {
        float ss = red[t];
        #pragma unroll
        for (int off = 16; off; off >>= 1)
            ss += __shfl_xor_sync(0xffffffffu, ss, off);
        if (t == 0) bc = ss;
    }
    __syncthreads();

    g_c[k * MUL + t] = e * (1.0f / bc);
}

// ---------------------------------------------------------------------------
extern "C" void kernel_launch(void* const* d_in, const int* in_sizes, int n_in,
                              void* d_out, int out_size)
{
    const float* x = (const float*)d_in[0];   // [256][1024][8] flat view
    const float* W = (const float*)d_in[1];   // [20][16][8]
    float* out = (float*)d_out;               // [256][20][16][1]

    const int F_SMEM = F_FLOATS * (int)sizeof(float);   // ~152 KB
    cudaFuncSetAttribute(fused_kernel,
                         cudaFuncAttributeMaxDynamicSharedMemorySize, F_SMEM);

    dim3 ugrid(16, 16);

    // iteration 0: xsum -> (y0 + tail + agree) -> softmax
    prep_xsum<<<B_TOT, 256>>>(x);
    u0_kernel<<<ugrid, U_THREADS>>>(x, W);
    softmax_kernel<<<NK, 1024>>>(0);

    // iteration 1
    fused_kernel<<<B_TOT / 2, F_THREADS, F_SMEM>>>(x, W, out, 0);
    update_kernel<<<ugrid, U_THREADS>>>(x);
    softmax_kernel<<<NK, 1024>>>(1);

    // iteration 2 (final -> write v)
    fused_kernel<<<B_TOT / 2, F_THREADS, F_SMEM>>>(x, W, out, 1);
}